// round 12
// baseline (speedup 1.0000x reference)
#include <cuda_runtime.h>
#include <cuda_fp16.h>
#include <cstdint>

#define NMAX 100000
#define EMAX 1600000
#define D 128

// ---- scratch (no allocations allowed -> __device__ globals) ----
__device__ int   g_deg[NMAX];
__device__ float g_dinv[NMAX];
__device__ int   g_colptr[NMAX + 1];
__device__ int   g_cursor[NMAX];
__device__ int   g_srow[EMAX];
__device__ uint2 g_hbuf[(size_t)NMAX * D / 4];   // fp16 features (8B per lane-slot)
__device__ uint2 g_zbuf[(size_t)NMAX * D / 4];
__device__ int   g_part[256];

__device__ __forceinline__ float to_tf32(float x) {
    float y;
    asm("cvt.rna.tf32.f32 %0, %1;" : "=f"(y) : "f"(x));
    return y;
}

__device__ __forceinline__ float4 h4f(uint2 u) {
    __half2 a = *reinterpret_cast<__half2*>(&u.x);
    __half2 b = *reinterpret_cast<__half2*>(&u.y);
    float2 fa = __half22float2(a), fb = __half22float2(b);
    return make_float4(fa.x, fa.y, fb.x, fb.y);
}

// ---------------- degree ----------------
__global__ void k_deg_init(int n) {
    int i = blockIdx.x * blockDim.x + threadIdx.x;
    if (i < n) g_deg[i] = 0;
}
__global__ void k_deg_count(const int* __restrict__ col, int e) {
    int i = blockIdx.x * blockDim.x + threadIdx.x;
    if (i < e) atomicAdd(&g_deg[col[i]], 1);
}

// ---------------- exclusive scan of g_deg -> g_colptr (+dinv fused) ----------------
#define SCAN_T 256
#define SCAN_I 8
#define SCAN_C (SCAN_T * SCAN_I)

__global__ void k_scan_partial(int n) {
    __shared__ int ss[SCAN_T];
    int b = blockIdx.x, tid = threadIdx.x;
    int base = b * SCAN_C + tid * SCAN_I;
    int s = 0;
    #pragma unroll
    for (int i = 0; i < SCAN_I; i++) {
        int idx = base + i;
        if (idx < n) s += g_deg[idx];
    }
    ss[tid] = s;
    __syncthreads();
    for (int off = SCAN_T / 2; off > 0; off >>= 1) {
        if (tid < off) ss[tid] += ss[tid + off];
        __syncthreads();
    }
    if (tid == 0) g_part[b] = ss[0];
}

__global__ void k_scan_offsets(int nb) {
    int lane = threadIdx.x;
    int a = (lane < nb) ? g_part[lane] : 0;
    int b = (lane + 32 < nb) ? g_part[lane + 32] : 0;
    int sa = a, sb = b;
    #pragma unroll
    for (int off = 1; off < 32; off <<= 1) {
        int ta = __shfl_up_sync(0xFFFFFFFF, sa, off);
        int tb = __shfl_up_sync(0xFFFFFFFF, sb, off);
        if (lane >= off) { sa += ta; sb += tb; }
    }
    int totA = __shfl_sync(0xFFFFFFFF, sa, 31);
    if (lane < nb) g_part[lane] = sa - a;
    if (lane + 32 < nb) g_part[lane + 32] = totA + sb - b;
}

__global__ void k_scan_final(int n, int e) {
    __shared__ int ss[SCAN_T];
    int b = blockIdx.x, tid = threadIdx.x;
    int base = b * SCAN_C + tid * SCAN_I;
    int vals[SCAN_I];
    int degs[SCAN_I];
    int local = 0;
    #pragma unroll
    for (int i = 0; i < SCAN_I; i++) {
        int idx = base + i;
        int v = (idx < n) ? g_deg[idx] : 0;
        degs[i] = v;
        vals[i] = local;
        local += v;
    }
    ss[tid] = local;
    __syncthreads();
    for (int off = 1; off < SCAN_T; off <<= 1) {
        int v = 0;
        if (tid >= off) v = ss[tid - off];
        __syncthreads();
        ss[tid] += v;
        __syncthreads();
    }
    int toff = g_part[b] + ss[tid] - local;
    #pragma unroll
    for (int i = 0; i < SCAN_I; i++) {
        int idx = base + i;
        if (idx < n) {
            int p = toff + vals[i];
            g_colptr[idx] = p;
            g_cursor[idx] = p;
            g_dinv[idx] = rsqrtf((float)(degs[i] + 1));
        }
    }
    if (b == 0 && tid == 0) g_colptr[n] = e;
}

// ---------------- CSR fill ----------------
__global__ void k_fill(const int* __restrict__ row, const int* __restrict__ col, int e) {
    int i = blockIdx.x * blockDim.x + threadIdx.x;
    if (i < e) {
        int p = atomicAdd(&g_cursor[col[i]], 1);
        g_srow[p] = row[i];
    }
}

// ---------------- tf32 mma.sync GEMM: C_fp16[n,128] = A[n,128] @ W[128,128] ----------------
#define AST 68
#define BST 136
#define GSMEM_FLOATS (128 * AST + 64 * BST)   // 69632 B

#define MMA_TF32(d, a, b) \
    asm volatile("mma.sync.aligned.m16n8k8.row.col.f32.tf32.tf32.f32 " \
        "{%0,%1,%2,%3}, {%4,%5,%6,%7}, {%8,%9}, {%0,%1,%2,%3};" \
        : "+f"((d)[0]), "+f"((d)[1]), "+f"((d)[2]), "+f"((d)[3]) \
        : "r"((a)[0]), "r"((a)[1]), "r"((a)[2]), "r"((a)[3]), \
          "r"((b)[0]), "r"((b)[1]))

__device__ __forceinline__ float4 load4(const float* p) { return *(const float4*)p; }
__device__ __forceinline__ float4 load4(const __half* p) {
    return h4f(*(const uint2*)p);
}

template <typename AT>
__global__ void __launch_bounds__(256) k_gemm_mma(const AT* __restrict__ A,
                                                  const float* __restrict__ W,
                                                  __half* __restrict__ C, int n) {
    extern __shared__ float smem[];
    float* As = smem;
    float* Bs = smem + 128 * AST;

    int tid = threadIdx.x;
    int wid = tid >> 5, lane = tid & 31;
    int gq = lane >> 2;
    int cq = lane & 3;
    int row0 = blockIdx.x << 7;
    int wm = (wid >> 2) << 6;
    int wn = (wid & 3) << 5;

    float acc[4][4][4];
    #pragma unroll
    for (int mt = 0; mt < 4; mt++)
        #pragma unroll
        for (int nt = 0; nt < 4; nt++)
            #pragma unroll
            for (int i = 0; i < 4; i++)
                acc[mt][nt][i] = 0.f;

    const uint32_t* Au = (const uint32_t*)As;
    const uint32_t* Bu = (const uint32_t*)Bs;

    for (int ch = 0; ch < 2; ch++) {
        int k0 = ch << 6;
        #pragma unroll
        for (int it = 0; it < 8; it++) {
            int t = tid + it * 256;
            int m = t >> 4, kq = t & 15;
            int gm = row0 + m;
            float4 v = make_float4(0.f, 0.f, 0.f, 0.f);
            if (gm < n) v = load4(A + (size_t)gm * D + k0 + kq * 4);
            v.x = to_tf32(v.x); v.y = to_tf32(v.y);
            v.z = to_tf32(v.z); v.w = to_tf32(v.w);
            *(float4*)(As + m * AST + kq * 4) = v;
        }
        #pragma unroll
        for (int it = 0; it < 8; it++) {
            int t = tid + it * 256;
            int k = t >> 5, nq = t & 31;
            float4 v = *(const float4*)(W + (size_t)(k0 + k) * D + nq * 4);
            v.x = to_tf32(v.x); v.y = to_tf32(v.y);
            v.z = to_tf32(v.z); v.w = to_tf32(v.w);
            *(float4*)(Bs + k * BST + nq * 4) = v;
        }
        __syncthreads();

        #pragma unroll
        for (int kt = 0; kt < 8; kt++) {
            int kl = kt << 3;
            uint32_t a[4][4];
            uint32_t b[4][2];
            #pragma unroll
            for (int mt = 0; mt < 4; mt++) {
                const uint32_t* ap = Au + (wm + (mt << 4)) * AST + kl;
                a[mt][0] = ap[gq * AST + cq];
                a[mt][1] = ap[(gq + 8) * AST + cq];
                a[mt][2] = ap[gq * AST + cq + 4];
                a[mt][3] = ap[(gq + 8) * AST + cq + 4];
            }
            #pragma unroll
            for (int nt = 0; nt < 4; nt++) {
                const uint32_t* bp = Bu + kl * BST + wn + (nt << 3);
                b[nt][0] = bp[cq * BST + gq];
                b[nt][1] = bp[(cq + 4) * BST + gq];
            }
            #pragma unroll
            for (int mt = 0; mt < 4; mt++)
                #pragma unroll
                for (int nt = 0; nt < 4; nt++)
                    MMA_TF32(acc[mt][nt], a[mt], b[nt]);
        }
        __syncthreads();
    }

    #pragma unroll
    for (int mt = 0; mt < 4; mt++) {
        int r0 = row0 + wm + (mt << 4) + gq;
        int r1 = r0 + 8;
        #pragma unroll
        for (int nt = 0; nt < 4; nt++) {
            int cc = wn + (nt << 3) + (cq << 1);
            if (r0 < n)
                *(__half2*)(C + (size_t)r0 * D + cc) =
                    __floats2half2_rn(acc[mt][nt][0], acc[mt][nt][1]);
            if (r1 < n)
                *(__half2*)(C + (size_t)r1 * D + cc) =
                    __floats2half2_rn(acc[mt][nt][2], acc[mt][nt][3]);
        }
    }
}

// ---------------- aggregation (fp16 gather, fp32 accumulate) ----------------
// one warp per node. Indices + dinv batch-loaded 32 at a time by lanes (off the
// critical chain), broadcast by shfl; feature rows prefetched 4-deep.
__device__ __forceinline__ void store4(float* p, float a, float b, float c, float d) {
    *(float4*)p = make_float4(a, b, c, d);
}
__device__ __forceinline__ void store4(__half* p, float a, float b, float c, float d) {
    *(__half2*)p = __floats2half2_rn(a, b);
    *(__half2*)(p + 2) = __floats2half2_rn(c, d);
}

template <typename OT>
__global__ void k_agg(const __half* __restrict__ h, const float* __restrict__ bias,
                      OT* __restrict__ out, int n, int do_relu) {
    int gt = blockIdx.x * blockDim.x + threadIdx.x;
    int c = gt >> 5;
    int lane = gt & 31;
    if (c >= n) return;

    float dc = g_dinv[c];
    const uint2* h4 = (const uint2*)h;
    float4 sv = h4f(h4[(size_t)c * 32 + lane]);

    // neighbor accumulator (scaled by dinv[r] only; dc factored out)
    float ax = 0.f, ay = 0.f, az = 0.f, aw = 0.f;

    int i = g_colptr[c];
    int end = g_colptr[c + 1];
    while (i < end) {
        int m = end - i;
        if (m > 32) m = 32;
        // batch: lane j holds index/weight of row i+j
        int r = (lane < m) ? g_srow[i + lane] : 0;
        float dv = (lane < m) ? g_dinv[r] : 0.f;

        uint2 pu[4];
        float pw[4];
        #pragma unroll
        for (int d0 = 0; d0 < 4; d0++) {
            if (d0 < m) {
                int rr = __shfl_sync(0xFFFFFFFF, r, d0);
                pw[d0] = __shfl_sync(0xFFFFFFFF, dv, d0);
                pu[d0] = h4[(size_t)rr * 32 + lane];
            } else {
                pw[d0] = 0.f;
                pu[d0] = make_uint2(0, 0);
            }
        }
        for (int j = 0; j < m; j++) {
            int dn = j + 4;
            uint2 un = make_uint2(0, 0);
            float wn = 0.f;
            if (dn < m) {
                int rr = __shfl_sync(0xFFFFFFFF, r, dn);
                wn = __shfl_sync(0xFFFFFFFF, dv, dn);
                un = h4[(size_t)rr * 32 + lane];
            }
            float4 f = h4f(pu[j & 3]);
            float w = pw[j & 3];
            ax += w * f.x; ay += w * f.y;
            az += w * f.z; aw += w * f.w;
            pu[j & 3] = un; pw[j & 3] = wn;
        }
        i += m;
    }

    // total = dc*neigh + dc^2*self + bias
    float s = dc * dc;
    float4 bv = ((const float4*)bias)[lane];
    ax = dc * ax + s * sv.x + bv.x;
    ay = dc * ay + s * sv.y + bv.y;
    az = dc * az + s * sv.z + bv.z;
    aw = dc * aw + s * sv.w + bv.w;
    if (do_relu) {
        ax = fmaxf(ax, 0.f); ay = fmaxf(ay, 0.f);
        az = fmaxf(az, 0.f); aw = fmaxf(aw, 0.f);
    }
    store4(out + (size_t)c * D + lane * 4, ax, ay, az, aw);
}

// ---------------- launch ----------------
extern "C" void kernel_launch(void* const* d_in, const int* in_sizes, int n_in,
                              void* d_out, int out_size) {
    const float* x  = (const float*)d_in[0];
    const int*   ei = (const int*)d_in[1];
    const float* W1 = (const float*)d_in[2];
    const float* b1 = (const float*)d_in[3];
    const float* W2 = (const float*)d_in[4];
    const float* b2 = (const float*)d_in[5];
    float* out = (float*)d_out;

    int n = in_sizes[0] / D;
    int e = in_sizes[1] / 2;
    const int* row = ei;
    const int* col = ei + e;

    void *ph = nullptr, *pz = nullptr;
    cudaGetSymbolAddress(&ph, g_hbuf);
    cudaGetSymbolAddress(&pz, g_zbuf);
    __half* h = (__half*)ph;
    __half* z = (__half*)pz;

    static int init_done = 0;
    static cudaStream_t s2 = nullptr;
    static cudaEvent_t ev_fork = nullptr, ev_join = nullptr;
    if (!init_done) {
        cudaFuncSetAttribute(k_gemm_mma<float>, cudaFuncAttributeMaxDynamicSharedMemorySize,
                             GSMEM_FLOATS * 4);
        cudaFuncSetAttribute(k_gemm_mma<__half>, cudaFuncAttributeMaxDynamicSharedMemorySize,
                             GSMEM_FLOATS * 4);
        if (cudaStreamCreateWithFlags(&s2, cudaStreamNonBlocking) != cudaSuccess) s2 = nullptr;
        if (cudaEventCreateWithFlags(&ev_fork, cudaEventDisableTiming) != cudaSuccess) ev_fork = nullptr;
        if (cudaEventCreateWithFlags(&ev_join, cudaEventDisableTiming) != cudaSuccess) ev_join = nullptr;
        init_done = 1;
    }
    bool fork = (s2 && ev_fork && ev_join);
    cudaStream_t sc = fork ? s2 : (cudaStream_t)0;

    int nb = (n + SCAN_C - 1) / SCAN_C;
    int gemm_blocks = (n + 127) / 128;
    int agg_blocks = (n * 32 + 255) / 256;

    if (fork) {
        cudaEventRecord(ev_fork, 0);
        cudaStreamWaitEvent(s2, ev_fork, 0);
    }

    // ---- CSR build chain (side stream when forked) ----
    k_deg_init<<<(n + 255) / 256, 256, 0, sc>>>(n);
    k_deg_count<<<(e + 255) / 256, 256, 0, sc>>>(col, e);
    k_scan_partial<<<nb, SCAN_T, 0, sc>>>(n);
    k_scan_offsets<<<1, 32, 0, sc>>>(nb);
    k_scan_final<<<nb, SCAN_T, 0, sc>>>(n, e);
    k_fill<<<(e + 255) / 256, 256, 0, sc>>>(row, col, e);

    if (fork) cudaEventRecord(ev_join, s2);

    // ---- GEMM1 (fp32 in, fp16 out) overlaps the CSR build ----
    k_gemm_mma<float><<<gemm_blocks, 256, GSMEM_FLOATS * 4>>>(x, W1, h, n);

    if (fork) cudaStreamWaitEvent((cudaStream_t)0, ev_join, 0);

    // layer 1 aggregate: z = relu(Ahat h + b1)   (fp16 out)
    k_agg<__half><<<agg_blocks, 256>>>(h, b1, z, n, 1);
    // layer 2: h = z @ W2 (fp16 in/out) ; out = Ahat h + b2 (fp32 out)
    k_gemm_mma<__half><<<gemm_blocks, 256, GSMEM_FLOATS * 4>>>(z, W2, h, n);
    k_agg<float><<<agg_blocks, 256>>>(h, b2, out, n, 0);
}

// round 13
// speedup vs baseline: 1.1466x; 1.1466x over previous
#include <cuda_runtime.h>
#include <cuda_fp16.h>
#include <cstdint>

#define NMAX 100000
#define EMAX 1600000
#define D 128

// ---- scratch (no allocations allowed -> __device__ globals) ----
__device__ int   g_deg[NMAX];
__device__ float g_dinv[NMAX];
__device__ int   g_colptr[NMAX + 1];
__device__ int   g_cursor[NMAX];
__device__ int2  g_edge[EMAX];                   // {src row, bits(dinv[src])}
__device__ uint2 g_hbuf[(size_t)NMAX * D / 4];   // fp16 features (8B per lane-slot)
__device__ uint2 g_zbuf[(size_t)NMAX * D / 4];
__device__ int   g_part[256];

__device__ __forceinline__ float to_tf32(float x) {
    float y;
    asm("cvt.rna.tf32.f32 %0, %1;" : "=f"(y) : "f"(x));
    return y;
}

__device__ __forceinline__ float4 h4f(uint2 u) {
    __half2 a = *reinterpret_cast<__half2*>(&u.x);
    __half2 b = *reinterpret_cast<__half2*>(&u.y);
    float2 fa = __half22float2(a), fb = __half22float2(b);
    return make_float4(fa.x, fa.y, fb.x, fb.y);
}

// ---------------- degree ----------------
__global__ void k_deg_init(int n) {
    int i = blockIdx.x * blockDim.x + threadIdx.x;
    if (i < n) g_deg[i] = 0;
}
__global__ void k_deg_count(const int* __restrict__ col, int e) {
    int i = blockIdx.x * blockDim.x + threadIdx.x;
    if (i < e) atomicAdd(&g_deg[col[i]], 1);
}

// ---------------- exclusive scan of g_deg -> g_colptr (+dinv fused) ----------------
#define SCAN_T 256
#define SCAN_I 8
#define SCAN_C (SCAN_T * SCAN_I)

__global__ void k_scan_partial(int n) {
    __shared__ int ss[SCAN_T];
    int b = blockIdx.x, tid = threadIdx.x;
    int base = b * SCAN_C + tid * SCAN_I;
    int s = 0;
    #pragma unroll
    for (int i = 0; i < SCAN_I; i++) {
        int idx = base + i;
        if (idx < n) s += g_deg[idx];
    }
    ss[tid] = s;
    __syncthreads();
    for (int off = SCAN_T / 2; off > 0; off >>= 1) {
        if (tid < off) ss[tid] += ss[tid + off];
        __syncthreads();
    }
    if (tid == 0) g_part[b] = ss[0];
}

__global__ void k_scan_offsets(int nb) {
    int lane = threadIdx.x;
    int a = (lane < nb) ? g_part[lane] : 0;
    int b = (lane + 32 < nb) ? g_part[lane + 32] : 0;
    int sa = a, sb = b;
    #pragma unroll
    for (int off = 1; off < 32; off <<= 1) {
        int ta = __shfl_up_sync(0xFFFFFFFF, sa, off);
        int tb = __shfl_up_sync(0xFFFFFFFF, sb, off);
        if (lane >= off) { sa += ta; sb += tb; }
    }
    int totA = __shfl_sync(0xFFFFFFFF, sa, 31);
    if (lane < nb) g_part[lane] = sa - a;
    if (lane + 32 < nb) g_part[lane + 32] = totA + sb - b;
}

__global__ void k_scan_final(int n, int e) {
    __shared__ int ss[SCAN_T];
    int b = blockIdx.x, tid = threadIdx.x;
    int base = b * SCAN_C + tid * SCAN_I;
    int vals[SCAN_I];
    int degs[SCAN_I];
    int local = 0;
    #pragma unroll
    for (int i = 0; i < SCAN_I; i++) {
        int idx = base + i;
        int v = (idx < n) ? g_deg[idx] : 0;
        degs[i] = v;
        vals[i] = local;
        local += v;
    }
    ss[tid] = local;
    __syncthreads();
    for (int off = 1; off < SCAN_T; off <<= 1) {
        int v = 0;
        if (tid >= off) v = ss[tid - off];
        __syncthreads();
        ss[tid] += v;
        __syncthreads();
    }
    int toff = g_part[b] + ss[tid] - local;
    #pragma unroll
    for (int i = 0; i < SCAN_I; i++) {
        int idx = base + i;
        if (idx < n) {
            int p = toff + vals[i];
            g_colptr[idx] = p;
            g_cursor[idx] = p;
            g_dinv[idx] = rsqrtf((float)(degs[i] + 1));
        }
    }
    if (b == 0 && tid == 0) g_colptr[n] = e;
}

// ---------------- CSR fill: self-contained edge records {src, dinv[src]} ----------------
__global__ void k_fill(const int* __restrict__ row, const int* __restrict__ col, int e) {
    int i = blockIdx.x * blockDim.x + threadIdx.x;
    if (i < e) {
        int r = row[i];
        float dv = g_dinv[r];
        int p = atomicAdd(&g_cursor[col[i]], 1);
        g_edge[p] = make_int2(r, __float_as_int(dv));
    }
}

// ---------------- tf32 mma.sync GEMM: C_fp16[n,128] = A[n,128] @ W[128,128] ----------------
#define AST 68
#define BST 136
#define GSMEM_FLOATS (128 * AST + 64 * BST)   // 69632 B

#define MMA_TF32(d, a, b) \
    asm volatile("mma.sync.aligned.m16n8k8.row.col.f32.tf32.tf32.f32 " \
        "{%0,%1,%2,%3}, {%4,%5,%6,%7}, {%8,%9}, {%0,%1,%2,%3};" \
        : "+f"((d)[0]), "+f"((d)[1]), "+f"((d)[2]), "+f"((d)[3]) \
        : "r"((a)[0]), "r"((a)[1]), "r"((a)[2]), "r"((a)[3]), \
          "r"((b)[0]), "r"((b)[1]))

__device__ __forceinline__ float4 load4(const float* p) { return *(const float4*)p; }
__device__ __forceinline__ float4 load4(const __half* p) {
    return h4f(*(const uint2*)p);
}

template <typename AT>
__global__ void __launch_bounds__(256) k_gemm_mma(const AT* __restrict__ A,
                                                  const float* __restrict__ W,
                                                  __half* __restrict__ C, int n) {
    extern __shared__ float smem[];
    float* As = smem;
    float* Bs = smem + 128 * AST;

    int tid = threadIdx.x;
    int wid = tid >> 5, lane = tid & 31;
    int gq = lane >> 2;
    int cq = lane & 3;
    int row0 = blockIdx.x << 7;
    int wm = (wid >> 2) << 6;
    int wn = (wid & 3) << 5;

    float acc[4][4][4];
    #pragma unroll
    for (int mt = 0; mt < 4; mt++)
        #pragma unroll
        for (int nt = 0; nt < 4; nt++)
            #pragma unroll
            for (int i = 0; i < 4; i++)
                acc[mt][nt][i] = 0.f;

    const uint32_t* Au = (const uint32_t*)As;
    const uint32_t* Bu = (const uint32_t*)Bs;

    for (int ch = 0; ch < 2; ch++) {
        int k0 = ch << 6;
        #pragma unroll
        for (int it = 0; it < 8; it++) {
            int t = tid + it * 256;
            int m = t >> 4, kq = t & 15;
            int gm = row0 + m;
            float4 v = make_float4(0.f, 0.f, 0.f, 0.f);
            if (gm < n) v = load4(A + (size_t)gm * D + k0 + kq * 4);
            v.x = to_tf32(v.x); v.y = to_tf32(v.y);
            v.z = to_tf32(v.z); v.w = to_tf32(v.w);
            *(float4*)(As + m * AST + kq * 4) = v;
        }
        #pragma unroll
        for (int it = 0; it < 8; it++) {
            int t = tid + it * 256;
            int k = t >> 5, nq = t & 31;
            float4 v = *(const float4*)(W + (size_t)(k0 + k) * D + nq * 4);
            v.x = to_tf32(v.x); v.y = to_tf32(v.y);
            v.z = to_tf32(v.z); v.w = to_tf32(v.w);
            *(float4*)(Bs + k * BST + nq * 4) = v;
        }
        __syncthreads();

        #pragma unroll
        for (int kt = 0; kt < 8; kt++) {
            int kl = kt << 3;
            uint32_t a[4][4];
            uint32_t b[4][2];
            #pragma unroll
            for (int mt = 0; mt < 4; mt++) {
                const uint32_t* ap = Au + (wm + (mt << 4)) * AST + kl;
                a[mt][0] = ap[gq * AST + cq];
                a[mt][1] = ap[(gq + 8) * AST + cq];
                a[mt][2] = ap[gq * AST + cq + 4];
                a[mt][3] = ap[(gq + 8) * AST + cq + 4];
            }
            #pragma unroll
            for (int nt = 0; nt < 4; nt++) {
                const uint32_t* bp = Bu + kl * BST + wn + (nt << 3);
                b[nt][0] = bp[cq * BST + gq];
                b[nt][1] = bp[(cq + 4) * BST + gq];
            }
            #pragma unroll
            for (int mt = 0; mt < 4; mt++)
                #pragma unroll
                for (int nt = 0; nt < 4; nt++)
                    MMA_TF32(acc[mt][nt], a[mt], b[nt]);
        }
        __syncthreads();
    }

    #pragma unroll
    for (int mt = 0; mt < 4; mt++) {
        int r0 = row0 + wm + (mt << 4) + gq;
        int r1 = r0 + 8;
        #pragma unroll
        for (int nt = 0; nt < 4; nt++) {
            int cc = wn + (nt << 3) + (cq << 1);
            if (r0 < n)
                *(__half2*)(C + (size_t)r0 * D + cc) =
                    __floats2half2_rn(acc[mt][nt][0], acc[mt][nt][1]);
            if (r1 < n)
                *(__half2*)(C + (size_t)r1 * D + cc) =
                    __floats2half2_rn(acc[mt][nt][2], acc[mt][nt][3]);
        }
    }
}

// ---------------- aggregation (fp16 gather, fp32 accumulate) ----------------
// one warp per node. Edge pairs (broadcast, sequential) prefetched 8-11 rows
// ahead; feature rows 4-7 ahead; consume 4 rows per block. All scalar rings.
__device__ __forceinline__ void store4(float* p, float a, float b, float c, float d) {
    *(float4*)p = make_float4(a, b, c, d);
}
__device__ __forceinline__ void store4(__half* p, float a, float b, float c, float d) {
    *(__half2*)p = __floats2half2_rn(a, b);
    *(__half2*)(p + 2) = __floats2half2_rn(c, d);
}

template <typename OT>
__global__ void k_agg(const __half* __restrict__ h, const float* __restrict__ bias,
                      OT* __restrict__ out, int n, int do_relu) {
    int gt = blockIdx.x * blockDim.x + threadIdx.x;
    int c = gt >> 5;
    int lane = gt & 31;
    if (c >= n) return;

    float dc = g_dinv[c];
    const uint2* h4p = (const uint2*)h;
    float4 sv = h4f(h4p[(size_t)c * 32 + lane]);

    int p0 = g_colptr[c];
    int deg = g_colptr[c + 1] - p0;
    const int2* ep = g_edge + p0;

    float ax = 0.f, ay = 0.f, az = 0.f, aw = 0.f;
    const uint2 ZU = make_uint2(0u, 0u);
    const int2 ZE = make_int2(0, 0);

    // prologue: features rows 0..3, edge-pair ring rows 4..7
    float w0 = 0.f, w1 = 0.f, w2 = 0.f, w3 = 0.f;
    uint2 u0 = ZU, u1 = ZU, u2 = ZU, u3 = ZU;
    if (0 < deg) { int2 t = ep[0]; w0 = __int_as_float(t.y); u0 = h4p[(size_t)t.x * 32 + lane]; }
    if (1 < deg) { int2 t = ep[1]; w1 = __int_as_float(t.y); u1 = h4p[(size_t)t.x * 32 + lane]; }
    if (2 < deg) { int2 t = ep[2]; w2 = __int_as_float(t.y); u2 = h4p[(size_t)t.x * 32 + lane]; }
    if (3 < deg) { int2 t = ep[3]; w3 = __int_as_float(t.y); u3 = h4p[(size_t)t.x * 32 + lane]; }
    int2 e4 = (4 < deg) ? ep[4] : ZE;
    int2 e5 = (5 < deg) ? ep[5] : ZE;
    int2 e6 = (6 < deg) ? ep[6] : ZE;
    int2 e7 = (7 < deg) ? ep[7] : ZE;

    for (int j = 0; j < deg; j += 4) {
        // issue next features (rows j+4..j+7) from the edge ring
        float nw0 = 0.f, nw1 = 0.f, nw2 = 0.f, nw3 = 0.f;
        uint2 nu0 = ZU, nu1 = ZU, nu2 = ZU, nu3 = ZU;
        if (j + 4 < deg) { nw0 = __int_as_float(e4.y); nu0 = h4p[(size_t)e4.x * 32 + lane]; }
        if (j + 5 < deg) { nw1 = __int_as_float(e5.y); nu1 = h4p[(size_t)e5.x * 32 + lane]; }
        if (j + 6 < deg) { nw2 = __int_as_float(e6.y); nu2 = h4p[(size_t)e6.x * 32 + lane]; }
        if (j + 7 < deg) { nw3 = __int_as_float(e7.y); nu3 = h4p[(size_t)e7.x * 32 + lane]; }
        // issue next edge pairs (rows j+8..j+11)
        e4 = (j + 8  < deg) ? ep[j + 8]  : ZE;
        e5 = (j + 9  < deg) ? ep[j + 9]  : ZE;
        e6 = (j + 10 < deg) ? ep[j + 10] : ZE;
        e7 = (j + 11 < deg) ? ep[j + 11] : ZE;
        // consume rows j..j+3
        float4 f;
        f = h4f(u0); ax += w0 * f.x; ay += w0 * f.y; az += w0 * f.z; aw += w0 * f.w;
        f = h4f(u1); ax += w1 * f.x; ay += w1 * f.y; az += w1 * f.z; aw += w1 * f.w;
        f = h4f(u2); ax += w2 * f.x; ay += w2 * f.y; az += w2 * f.z; aw += w2 * f.w;
        f = h4f(u3); ax += w3 * f.x; ay += w3 * f.y; az += w3 * f.z; aw += w3 * f.w;
        u0 = nu0; w0 = nw0; u1 = nu1; w1 = nw1;
        u2 = nu2; w2 = nw2; u3 = nu3; w3 = nw3;
    }

    // total = dc*Σ(dinv_r·h_r) + dc^2*h_c + bias
    float s = dc * dc;
    float4 bv = ((const float4*)bias)[lane];
    ax = dc * ax + s * sv.x + bv.x;
    ay = dc * ay + s * sv.y + bv.y;
    az = dc * az + s * sv.z + bv.z;
    aw = dc * aw + s * sv.w + bv.w;
    if (do_relu) {
        ax = fmaxf(ax, 0.f); ay = fmaxf(ay, 0.f);
        az = fmaxf(az, 0.f); aw = fmaxf(aw, 0.f);
    }
    store4(out + (size_t)c * D + lane * 4, ax, ay, az, aw);
}

// ---------------- launch ----------------
extern "C" void kernel_launch(void* const* d_in, const int* in_sizes, int n_in,
                              void* d_out, int out_size) {
    const float* x  = (const float*)d_in[0];
    const int*   ei = (const int*)d_in[1];
    const float* W1 = (const float*)d_in[2];
    const float* b1 = (const float*)d_in[3];
    const float* W2 = (const float*)d_in[4];
    const float* b2 = (const float*)d_in[5];
    float* out = (float*)d_out;

    int n = in_sizes[0] / D;
    int e = in_sizes[1] / 2;
    const int* row = ei;
    const int* col = ei + e;

    void *ph = nullptr, *pz = nullptr;
    cudaGetSymbolAddress(&ph, g_hbuf);
    cudaGetSymbolAddress(&pz, g_zbuf);
    __half* h = (__half*)ph;
    __half* z = (__half*)pz;

    static int init_done = 0;
    static cudaStream_t s2 = nullptr;
    static cudaEvent_t ev_fork = nullptr, ev_join = nullptr;
    if (!init_done) {
        cudaFuncSetAttribute(k_gemm_mma<float>, cudaFuncAttributeMaxDynamicSharedMemorySize,
                             GSMEM_FLOATS * 4);
        cudaFuncSetAttribute(k_gemm_mma<__half>, cudaFuncAttributeMaxDynamicSharedMemorySize,
                             GSMEM_FLOATS * 4);
        if (cudaStreamCreateWithFlags(&s2, cudaStreamNonBlocking) != cudaSuccess) s2 = nullptr;
        if (cudaEventCreateWithFlags(&ev_fork, cudaEventDisableTiming) != cudaSuccess) ev_fork = nullptr;
        if (cudaEventCreateWithFlags(&ev_join, cudaEventDisableTiming) != cudaSuccess) ev_join = nullptr;
        init_done = 1;
    }
    bool fork = (s2 && ev_fork && ev_join);
    cudaStream_t sc = fork ? s2 : (cudaStream_t)0;

    int nb = (n + SCAN_C - 1) / SCAN_C;
    int gemm_blocks = (n + 127) / 128;
    int agg_blocks = (n * 32 + 255) / 256;

    if (fork) {
        cudaEventRecord(ev_fork, 0);
        cudaStreamWaitEvent(s2, ev_fork, 0);
    }

    // ---- CSR build chain (side stream when forked) ----
    k_deg_init<<<(n + 255) / 256, 256, 0, sc>>>(n);
    k_deg_count<<<(e + 255) / 256, 256, 0, sc>>>(col, e);
    k_scan_partial<<<nb, SCAN_T, 0, sc>>>(n);
    k_scan_offsets<<<1, 32, 0, sc>>>(nb);
    k_scan_final<<<nb, SCAN_T, 0, sc>>>(n, e);
    k_fill<<<(e + 255) / 256, 256, 0, sc>>>(row, col, e);

    if (fork) cudaEventRecord(ev_join, s2);

    // ---- GEMM1 (fp32 in, fp16 out) overlaps the CSR build ----
    k_gemm_mma<float><<<gemm_blocks, 256, GSMEM_FLOATS * 4>>>(x, W1, h, n);

    if (fork) cudaStreamWaitEvent((cudaStream_t)0, ev_join, 0);

    // layer 1 aggregate: z = relu(Ahat h + b1)   (fp16 out)
    k_agg<__half><<<agg_blocks, 256>>>(h, b1, z, n, 1);
    // layer 2: h = z @ W2 (fp16 in/out) ; out = Ahat h + b2 (fp32 out)
    k_gemm_mma<__half><<<gemm_blocks, 256, GSMEM_FLOATS * 4>>>(z, W2, h, n);
    k_agg<float><<<agg_blocks, 256>>>(h, b2, out, n, 0);
}

// round 14
// speedup vs baseline: 1.2675x; 1.1054x over previous
#include <cuda_runtime.h>
#include <cuda_fp16.h>
#include <cstdint>

#define NMAX 100000
#define EMAX 1600000
#define D 128

// ---- scratch (no allocations allowed -> __device__ globals) ----
__device__ int   g_deg[NMAX];                    // zero at load; re-zeroed by agg2 each call
__device__ float g_dinv[NMAX];
__device__ int   g_colptr[NMAX + 1];
__device__ int   g_cursor[NMAX];
__device__ int2  g_edge[EMAX];                   // {src row, bits(dinv[src])}
__device__ uint2 g_hbuf[(size_t)NMAX * D / 4];   // fp16 features (8B per lane-slot)
__device__ uint2 g_zbuf[(size_t)NMAX * D / 4];
__device__ int   g_part[256];

__device__ __forceinline__ float to_tf32(float x) {
    float y;
    asm("cvt.rna.tf32.f32 %0, %1;" : "=f"(y) : "f"(x));
    return y;
}

__device__ __forceinline__ float4 h4f(uint2 u) {
    __half2 a = *reinterpret_cast<__half2*>(&u.x);
    __half2 b = *reinterpret_cast<__half2*>(&u.y);
    float2 fa = __half22float2(a), fb = __half22float2(b);
    return make_float4(fa.x, fa.y, fb.x, fb.y);
}

// ---------------- degree count (g_deg is pre-zeroed: load-time or by agg2) ----------------
__global__ void k_deg_count(const int* __restrict__ col, int e) {
    int i = blockIdx.x * blockDim.x + threadIdx.x;
    if (i < e) atomicAdd(&g_deg[col[i]], 1);
}

// ---------------- scan of g_deg -> g_colptr (+dinv fused) ----------------
#define SCAN_T 256
#define SCAN_I 8
#define SCAN_C (SCAN_T * SCAN_I)

__global__ void k_scan_partial(int n) {
    __shared__ int ss[SCAN_T];
    int b = blockIdx.x, tid = threadIdx.x;
    int base = b * SCAN_C + tid * SCAN_I;
    int s = 0;
    #pragma unroll
    for (int i = 0; i < SCAN_I; i++) {
        int idx = base + i;
        if (idx < n) s += g_deg[idx];
    }
    ss[tid] = s;
    __syncthreads();
    for (int off = SCAN_T / 2; off > 0; off >>= 1) {
        if (tid < off) ss[tid] += ss[tid + off];
        __syncthreads();
    }
    if (tid == 0) g_part[b] = ss[0];
}

// scan_final also computes its own block offset (sum of g_part below it)
__global__ void k_scan_final(int n, int e) {
    __shared__ int ss[SCAN_T];
    __shared__ int s_off;
    int b = blockIdx.x, tid = threadIdx.x;

    // block offset = sum_{j<b} g_part[j]
    ss[tid] = (tid < b) ? g_part[tid] : 0;
    __syncthreads();
    for (int off = SCAN_T / 2; off > 0; off >>= 1) {
        if (tid < off) ss[tid] += ss[tid + off];
        __syncthreads();
    }
    if (tid == 0) s_off = ss[0];
    __syncthreads();

    int base = b * SCAN_C + tid * SCAN_I;
    int vals[SCAN_I];
    int degs[SCAN_I];
    int local = 0;
    #pragma unroll
    for (int i = 0; i < SCAN_I; i++) {
        int idx = base + i;
        int v = (idx < n) ? g_deg[idx] : 0;
        degs[i] = v;
        vals[i] = local;
        local += v;
    }
    ss[tid] = local;
    __syncthreads();
    for (int off = 1; off < SCAN_T; off <<= 1) {
        int v = 0;
        if (tid >= off) v = ss[tid - off];
        __syncthreads();
        ss[tid] += v;
        __syncthreads();
    }
    int toff = s_off + ss[tid] - local;
    #pragma unroll
    for (int i = 0; i < SCAN_I; i++) {
        int idx = base + i;
        if (idx < n) {
            int p = toff + vals[i];
            g_colptr[idx] = p;
            g_cursor[idx] = p;
            g_dinv[idx] = rsqrtf((float)(degs[i] + 1));
        }
    }
    if (b == 0 && tid == 0) g_colptr[n] = e;
}

// ---------------- CSR fill: self-contained edge records {src, dinv[src]} ----------------
__global__ void k_fill(const int* __restrict__ row, const int* __restrict__ col, int e) {
    int i = blockIdx.x * blockDim.x + threadIdx.x;
    if (i < e) {
        int r = row[i];
        float dv = g_dinv[r];
        int p = atomicAdd(&g_cursor[col[i]], 1);
        g_edge[p] = make_int2(r, __float_as_int(dv));
    }
}

// ---------------- tf32 mma.sync GEMM: C_fp16[n,128] = A[n,128] @ W[128,128] ----------------
#define AST 68
#define BST 136
#define GSMEM_FLOATS (128 * AST + 64 * BST)   // 69632 B

#define MMA_TF32(d, a, b) \
    asm volatile("mma.sync.aligned.m16n8k8.row.col.f32.tf32.tf32.f32 " \
        "{%0,%1,%2,%3}, {%4,%5,%6,%7}, {%8,%9}, {%0,%1,%2,%3};" \
        : "+f"((d)[0]), "+f"((d)[1]), "+f"((d)[2]), "+f"((d)[3]) \
        : "r"((a)[0]), "r"((a)[1]), "r"((a)[2]), "r"((a)[3]), \
          "r"((b)[0]), "r"((b)[1]))

__device__ __forceinline__ float4 load4(const float* p) { return *(const float4*)p; }
__device__ __forceinline__ float4 load4(const __half* p) {
    return h4f(*(const uint2*)p);
}

template <typename AT>
__global__ void __launch_bounds__(256) k_gemm_mma(const AT* __restrict__ A,
                                                  const float* __restrict__ W,
                                                  __half* __restrict__ C, int n) {
    extern __shared__ float smem[];
    float* As = smem;
    float* Bs = smem + 128 * AST;

    int tid = threadIdx.x;
    int wid = tid >> 5, lane = tid & 31;
    int gq = lane >> 2;
    int cq = lane & 3;
    int row0 = blockIdx.x << 7;
    int wm = (wid >> 2) << 6;
    int wn = (wid & 3) << 5;

    float acc[4][4][4];
    #pragma unroll
    for (int mt = 0; mt < 4; mt++)
        #pragma unroll
        for (int nt = 0; nt < 4; nt++)
            #pragma unroll
            for (int i = 0; i < 4; i++)
                acc[mt][nt][i] = 0.f;

    const uint32_t* Au = (const uint32_t*)As;
    const uint32_t* Bu = (const uint32_t*)Bs;

    for (int ch = 0; ch < 2; ch++) {
        int k0 = ch << 6;
        #pragma unroll
        for (int it = 0; it < 8; it++) {
            int t = tid + it * 256;
            int m = t >> 4, kq = t & 15;
            int gm = row0 + m;
            float4 v = make_float4(0.f, 0.f, 0.f, 0.f);
            if (gm < n) v = load4(A + (size_t)gm * D + k0 + kq * 4);
            v.x = to_tf32(v.x); v.y = to_tf32(v.y);
            v.z = to_tf32(v.z); v.w = to_tf32(v.w);
            *(float4*)(As + m * AST + kq * 4) = v;
        }
        #pragma unroll
        for (int it = 0; it < 8; it++) {
            int t = tid + it * 256;
            int k = t >> 5, nq = t & 31;
            float4 v = *(const float4*)(W + (size_t)(k0 + k) * D + nq * 4);
            v.x = to_tf32(v.x); v.y = to_tf32(v.y);
            v.z = to_tf32(v.z); v.w = to_tf32(v.w);
            *(float4*)(Bs + k * BST + nq * 4) = v;
        }
        __syncthreads();

        #pragma unroll
        for (int kt = 0; kt < 8; kt++) {
            int kl = kt << 3;
            uint32_t a[4][4];
            uint32_t b[4][2];
            #pragma unroll
            for (int mt = 0; mt < 4; mt++) {
                const uint32_t* ap = Au + (wm + (mt << 4)) * AST + kl;
                a[mt][0] = ap[gq * AST + cq];
                a[mt][1] = ap[(gq + 8) * AST + cq];
                a[mt][2] = ap[gq * AST + cq + 4];
                a[mt][3] = ap[(gq + 8) * AST + cq + 4];
            }
            #pragma unroll
            for (int nt = 0; nt < 4; nt++) {
                const uint32_t* bp = Bu + kl * BST + wn + (nt << 3);
                b[nt][0] = bp[cq * BST + gq];
                b[nt][1] = bp[(cq + 4) * BST + gq];
            }
            #pragma unroll
            for (int mt = 0; mt < 4; mt++)
                #pragma unroll
                for (int nt = 0; nt < 4; nt++)
                    MMA_TF32(acc[mt][nt], a[mt], b[nt]);
        }
        __syncthreads();
    }

    #pragma unroll
    for (int mt = 0; mt < 4; mt++) {
        int r0 = row0 + wm + (mt << 4) + gq;
        int r1 = r0 + 8;
        #pragma unroll
        for (int nt = 0; nt < 4; nt++) {
            int cc = wn + (nt << 3) + (cq << 1);
            if (r0 < n)
                *(__half2*)(C + (size_t)r0 * D + cc) =
                    __floats2half2_rn(acc[mt][nt][0], acc[mt][nt][1]);
            if (r1 < n)
                *(__half2*)(C + (size_t)r1 * D + cc) =
                    __floats2half2_rn(acc[mt][nt][2], acc[mt][nt][3]);
        }
    }
}

// ---------------- aggregation (fp16 gather, fp32 accumulate) ----------------
// one warp per node, R10's proven 2-deep pipeline; edge records carry dinv.
__device__ __forceinline__ void store4(float* p, float a, float b, float c, float d) {
    *(float4*)p = make_float4(a, b, c, d);
}
__device__ __forceinline__ void store4(__half* p, float a, float b, float c, float d) {
    *(__half2*)p = __floats2half2_rn(a, b);
    *(__half2*)(p + 2) = __floats2half2_rn(c, d);
}

template <typename OT>
__global__ void k_agg(const __half* __restrict__ h, const float* __restrict__ bias,
                      OT* __restrict__ out, int n, int do_relu, int zero_deg) {
    int gt = blockIdx.x * blockDim.x + threadIdx.x;
    int c = gt >> 5;
    int lane = gt & 31;
    if (c >= n) return;

    float dc = g_dinv[c];
    const uint2* h4p = (const uint2*)h;
    float4 sv = h4f(h4p[(size_t)c * 32 + lane]);
    const int2* ep = g_edge;

    float ax = 0.f, ay = 0.f, az = 0.f, aw = 0.f;
    const uint2 ZU = make_uint2(0u, 0u);

    int i = g_colptr[c];
    int end = g_colptr[c + 1];
    uint2 u0 = ZU, u1 = ZU;
    float w0 = 0.f, w1 = 0.f;
    if (i < end) {
        int2 t = ep[i];
        w0 = __int_as_float(t.y);
        u0 = h4p[(size_t)t.x * 32 + lane];
    }
    if (i + 1 < end) {
        int2 t = ep[i + 1];
        w1 = __int_as_float(t.y);
        u1 = h4p[(size_t)t.x * 32 + lane];
    }
    for (; i < end; i++) {
        uint2 u2 = ZU;
        float w2 = 0.f;
        if (i + 2 < end) {
            int2 t = ep[i + 2];
            w2 = __int_as_float(t.y);
            u2 = h4p[(size_t)t.x * 32 + lane];
        }
        float4 f = h4f(u0);
        ax += w0 * f.x; ay += w0 * f.y;
        az += w0 * f.z; aw += w0 * f.w;
        u0 = u1; w0 = w1;
        u1 = u2; w1 = w2;
    }

    // total = dc*Σ(dinv_r·h_r) + dc^2*h_c + bias
    float s = dc * dc;
    float4 bv = ((const float4*)bias)[lane];
    ax = dc * ax + s * sv.x + bv.x;
    ay = dc * ay + s * sv.y + bv.y;
    az = dc * az + s * sv.z + bv.z;
    aw = dc * aw + s * sv.w + bv.w;
    if (do_relu) {
        ax = fmaxf(ax, 0.f); ay = fmaxf(ay, 0.f);
        az = fmaxf(az, 0.f); aw = fmaxf(aw, 0.f);
    }
    store4(out + (size_t)c * D + lane * 4, ax, ay, az, aw);

    // restore g_deg = 0 for the next call (replaces k_deg_init launch)
    if (zero_deg && lane == 0) g_deg[c] = 0;
}

// ---------------- launch ----------------
extern "C" void kernel_launch(void* const* d_in, const int* in_sizes, int n_in,
                              void* d_out, int out_size) {
    const float* x  = (const float*)d_in[0];
    const int*   ei = (const int*)d_in[1];
    const float* W1 = (const float*)d_in[2];
    const float* b1 = (const float*)d_in[3];
    const float* W2 = (const float*)d_in[4];
    const float* b2 = (const float*)d_in[5];
    float* out = (float*)d_out;

    int n = in_sizes[0] / D;
    int e = in_sizes[1] / 2;
    const int* row = ei;
    const int* col = ei + e;

    void *ph = nullptr, *pz = nullptr;
    cudaGetSymbolAddress(&ph, g_hbuf);
    cudaGetSymbolAddress(&pz, g_zbuf);
    __half* h = (__half*)ph;
    __half* z = (__half*)pz;

    static int init_done = 0;
    static cudaStream_t s2 = nullptr;
    static cudaEvent_t ev_fork = nullptr, ev_join = nullptr;
    if (!init_done) {
        cudaFuncSetAttribute(k_gemm_mma<float>, cudaFuncAttributeMaxDynamicSharedMemorySize,
                             GSMEM_FLOATS * 4);
        cudaFuncSetAttribute(k_gemm_mma<__half>, cudaFuncAttributeMaxDynamicSharedMemorySize,
                             GSMEM_FLOATS * 4);
        if (cudaStreamCreateWithFlags(&s2, cudaStreamNonBlocking) != cudaSuccess) s2 = nullptr;
        if (cudaEventCreateWithFlags(&ev_fork, cudaEventDisableTiming) != cudaSuccess) ev_fork = nullptr;
        if (cudaEventCreateWithFlags(&ev_join, cudaEventDisableTiming) != cudaSuccess) ev_join = nullptr;
        init_done = 1;
    }
    bool fork = (s2 && ev_fork && ev_join);
    cudaStream_t sc = fork ? s2 : (cudaStream_t)0;

    int nb = (n + SCAN_C - 1) / SCAN_C;
    int gemm_blocks = (n + 127) / 128;
    int agg_blocks = (n * 32 + 255) / 256;

    if (fork) {
        cudaEventRecord(ev_fork, 0);
        cudaStreamWaitEvent(s2, ev_fork, 0);
    }

    // ---- CSR build chain (side stream when forked); g_deg already zeroed ----
    k_deg_count<<<(e + 255) / 256, 256, 0, sc>>>(col, e);
    k_scan_partial<<<nb, SCAN_T, 0, sc>>>(n);
    k_scan_final<<<nb, SCAN_T, 0, sc>>>(n, e);
    k_fill<<<(e + 255) / 256, 256, 0, sc>>>(row, col, e);

    if (fork) cudaEventRecord(ev_join, s2);

    // ---- GEMM1 (fp32 in, fp16 out) overlaps the CSR build ----
    k_gemm_mma<float><<<gemm_blocks, 256, GSMEM_FLOATS * 4>>>(x, W1, h, n);

    if (fork) cudaStreamWaitEvent((cudaStream_t)0, ev_join, 0);

    // layer 1 aggregate: z = relu(Ahat h + b1)   (fp16 out)
    k_agg<__half><<<agg_blocks, 256>>>(h, b1, z, n, 1, 0);
    // layer 2: h = z @ W2 (fp16 in/out) ; out = Ahat h + b2 (fp32 out)
    k_gemm_mma<__half><<<gemm_blocks, 256, GSMEM_FLOATS * 4>>>(z, W2, h, n);
    k_agg<float><<<agg_blocks, 256>>>(h, b2, out, n, 0, 1);
}